// round 16
// baseline (speedup 1.0000x reference)
#include <cuda_runtime.h>
#include <cuda_bf16.h>
#include <cstdint>

#define NN  100000
#define EE  800000
#define DD  96
#define NRD 102   // D + XD

// ---- scratch (device globals; no allocation allowed) ----
__device__ __align__(16) float4 g_num4[NN * 24];
__device__ float  g_den[NN];
__device__ int    g_tailflag[NN];
__device__ __align__(16) float g_P[NN * DD];
__device__ __align__(16) float g_Q[NN * DD];
__device__ __align__(16) uint4 g_W3hi[96 * 12];     // bf16 [96 o][96 k]
__device__ __align__(16) uint4 g_W3lo[96 * 12];
__device__ __align__(16) uint4 g_W12hi[192 * 16];   // bf16 [192 n][128 k pad]
__device__ __align__(16) uint4 g_W12lo[192 * 16];

__device__ __forceinline__ uint32_t smem_u32(const void* p) {
    uint32_t a;
    asm("{ .reg .u64 t; cvta.to.shared.u64 t, %1; cvt.u32.u64 %0, t; }" : "=r"(a) : "l"(p));
    return a;
}

// ---------------------------------------------------------------------------
// bf16 split helpers
// ---------------------------------------------------------------------------
__device__ __forceinline__ void split4(float4 v, uint2& hi, uint2& lo) {
    uint32_t h01, h23, l01, l23;
    asm("cvt.rn.bf16x2.f32 %0, %1, %2;" : "=r"(h01) : "f"(v.y), "f"(v.x));
    asm("cvt.rn.bf16x2.f32 %0, %1, %2;" : "=r"(h23) : "f"(v.w), "f"(v.z));
    float r0 = v.x - __uint_as_float(h01 << 16);
    float r1 = v.y - __uint_as_float(h01 & 0xFFFF0000u);
    float r2 = v.z - __uint_as_float(h23 << 16);
    float r3 = v.w - __uint_as_float(h23 & 0xFFFF0000u);
    asm("cvt.rn.bf16x2.f32 %0, %1, %2;" : "=r"(l01) : "f"(r1), "f"(r0));
    asm("cvt.rn.bf16x2.f32 %0, %1, %2;" : "=r"(l23) : "f"(r3), "f"(r2));
    hi = make_uint2(h01, h23); lo = make_uint2(l01, l23);
}
__device__ __forceinline__ void split2(float f0, float f1, uint32_t& hi, uint32_t& lo) {
    asm("cvt.rn.bf16x2.f32 %0, %1, %2;" : "=r"(hi) : "f"(f1), "f"(f0));
    float r0 = f0 - __uint_as_float(hi << 16);
    float r1 = f1 - __uint_as_float(hi & 0xFFFF0000u);
    asm("cvt.rn.bf16x2.f32 %0, %1, %2;" : "=r"(lo) : "f"(r1), "f"(r0));
}

// ---------------------------------------------------------------------------
// K0: zero accumulators + tail flags; block 0 pre-splits W3 and W1|W2
// ---------------------------------------------------------------------------
__global__ void init_k(const float* __restrict__ W) {
    if (blockIdx.x == 0) {
        for (int i = threadIdx.x; i < 96 * 24; i += 256) {
            int o = i / 24, q = i % 24;
            float4 v = *(const float4*)(W + o * 300 + 204 + q * 4);
            uint2 hi, lo;
            split4(v, hi, lo);
            *((uint2*)g_W3hi + o * 24 + q) = hi;
            *((uint2*)g_W3lo + o * 24 + q) = lo;
        }
        for (int i = threadIdx.x; i < 192 * 64; i += 256) {
            int n = i >> 6, kp = i & 63, k = kp * 2;
            const float* src = (n < 96) ? (W + n * 300 + k) : (W + (n - 96) * 300 + 102 + k);
            float f0 = (k < 102) ? src[0] : 0.f;
            float f1 = (k + 1 < 102) ? src[1] : 0.f;
            uint32_t hi, lo;
            split2(f0, f1, hi, lo);
            ((uint32_t*)g_W12hi)[i] = hi;
            ((uint32_t*)g_W12lo)[i] = lo;
        }
    }
    int i = blockIdx.x * 256 + threadIdx.x;
    if (i < NN * 24) g_num4[i] = make_float4(0.f, 0.f, 0.f, 0.f);
    if (i < NN)      { g_den[i] = 0.f; g_tailflag[i] = 0; }
}

// ---------------------------------------------------------------------------
// K1: masked scatter-sum — 12 threads per edge (2 quads each), streaming attr
// ---------------------------------------------------------------------------
__global__ void scatter_k(const int* __restrict__ ei,
                          const float* __restrict__ attr,
                          const float* __restrict__ mask,
                          const int* __restrict__ tails) {
    if (blockIdx.x == 0 && threadIdx.x < 128)
        g_tailflag[tails[threadIdx.x]] = 1;
    int i = blockIdx.x * 256 + threadIdx.x;
    if (i >= EE * 12) return;
    int e = i / 12;
    int q2 = i - e * 12;                     // handles quads 2*q2, 2*q2+1
    int c = ei[EE + e];
    float m = mask[e];
    const float4* src = (const float4*)(attr + (size_t)e * 96) + q2 * 2;
    float4 v0 = __ldcs(src);
    float4 v1 = __ldcs(src + 1);
    float* dst = ((float*)g_num4) + (size_t)c * 96 + q2 * 8;
    asm volatile("red.global.add.v4.f32 [%0], {%1,%2,%3,%4};"
                 :: "l"(dst), "f"(v0.x * m), "f"(v0.y * m), "f"(v0.z * m), "f"(v0.w * m)
                 : "memory");
    asm volatile("red.global.add.v4.f32 [%0], {%1,%2,%3,%4};"
                 :: "l"(dst + 4), "f"(v1.x * m), "f"(v1.y * m), "f"(v1.z * m), "f"(v1.w * m)
                 : "memory");
    if (q2 == 0) atomicAdd(&g_den[c], m);
}

// ---------------------------------------------------------------------------
// K2: finalize — num/(den+1) cols 0..95, x cols 96..101, tail blend fused
// ---------------------------------------------------------------------------
__global__ void finalize_k(const float* __restrict__ x,
                           float* __restrict__ node_out,
                           const int* __restrict__ change,
                           const int* __restrict__ is_support,
                           const float* __restrict__ stail) {
    int i = blockIdx.x * 256 + threadIdx.x;
    if (i >= NN * 26) return;
    int n = i / 26;
    int q = i - n * 26;
    bool bl = g_tailflag[n] && change[0] && !is_support[0];
    if (q < 24) {
        float inv = 1.f / (g_den[n] + 1.f);
        float4 v = g_num4[n * 24 + q];
        float o0 = v.x * inv, o1 = v.y * inv, o2 = v.z * inv, o3 = v.w * inv;
        int col = q * 4;
        if (bl) {
            o0 = 0.1f * stail[col]     + 0.9f * o0;
            o1 = 0.1f * stail[col + 1] + 0.9f * o1;
            o2 = 0.1f * stail[col + 2] + 0.9f * o2;
            o3 = 0.1f * stail[col + 3] + 0.9f * o3;
        }
        float* dst = node_out + (size_t)n * NRD + col;
        dst[0] = o0; dst[1] = o1; dst[2] = o2; dst[3] = o3;
    } else {
        int j0 = (q - 24) * 3;
        #pragma unroll
        for (int j = 0; j < 3; j++) {
            int d = 96 + j0 + j;
            float o = x[(size_t)n * 6 + j0 + j];
            if (bl) o = 0.1f * stail[d] + 0.9f * o;
            node_out[(size_t)n * NRD + d] = o;
        }
    }
}

// ---------------------------------------------------------------------------
// K3: tail-row blend — SUPPORT PATH ONLY; early-exit otherwise.
// ---------------------------------------------------------------------------
__global__ void blend_k(const int* __restrict__ change,
                        const int* __restrict__ is_support,
                        const int* __restrict__ tails,
                        float* __restrict__ node_out) {
    if (change[0] == 0 || is_support[0] == 0) return;
    const int TOT = 128 * NRD;
    int tid = threadIdx.x;
    float vals[13];
    int   addr[13];
    short dim[13];
    int cnt = 0;
    for (int i = tid; i < TOT; i += 1024) {
        int t = i / NRD, d = i - t * NRD;
        int node = tails[t];
        addr[cnt] = node * NRD + d;
        dim[cnt]  = (short)d;
        vals[cnt] = node_out[addr[cnt]];
        cnt++;
    }
    __shared__ float ssum[NRD];
    for (int d = tid; d < NRD; d += 1024) ssum[d] = 0.f;
    __syncthreads();
    for (int j = 0; j < cnt; j++) atomicAdd(&ssum[dim[j]], vals[j]);
    __syncthreads();
    for (int j = 0; j < cnt; j++)
        node_out[addr[j]] = ssum[dim[j]] * (1.f / 128.f);
}

// ---------------------------------------------------------------------------
// shared MMA helpers
// ---------------------------------------------------------------------------
__device__ __forceinline__ void ldsm4(uint32_t addr, uint32_t* r) {
    asm volatile("ldmatrix.sync.aligned.m8n8.x4.shared.b16 {%0,%1,%2,%3}, [%4];"
                 : "=r"(r[0]), "=r"(r[1]), "=r"(r[2]), "=r"(r[3]) : "r"(addr));
}
__device__ __forceinline__ void mma_bf16(float4& c, const uint32_t* a,
                                         uint32_t b0, uint32_t b1) {
    asm volatile(
        "mma.sync.aligned.m16n8k16.row.col.f32.bf16.bf16.f32 "
        "{%0,%1,%2,%3}, {%4,%5,%6,%7}, {%8,%9}, {%0,%1,%2,%3};"
        : "+f"(c.x), "+f"(c.y), "+f"(c.z), "+f"(c.w)
        : "r"(a[0]), "r"(a[1]), "r"(a[2]), "r"(a[3]), "r"(b0), "r"(b1));
}

#define RS 80           // A row stride bytes (64B data + 16B pad)

// ---------------------------------------------------------------------------
// K4: P|Q fused GEMM via HMMA bf16 3-term split (proven R13 version)
// ---------------------------------------------------------------------------
__global__ __launch_bounds__(256, 2) void pq_mma(const float* __restrict__ node_rep) {
    __shared__ __align__(16) char sAhi[64 * RS];
    __shared__ __align__(16) char sAlo[64 * RS];
    __shared__ __align__(16) char sBhi[192 * RS];
    __shared__ __align__(16) char sBlo[192 * RS];

    int tid = threadIdx.x, lane = tid & 31, w = tid >> 5;
    int n0 = blockIdx.x * 64;
    int w4 = w & 3, nh = w >> 2;

    uint32_t aHi = smem_u32(sAhi), aLo = smem_u32(sAlo);
    uint32_t bHi = smem_u32(sBhi), bLo = smem_u32(sBlo);

    uint32_t aoff = (uint32_t)(w4 * 16 + (lane & 15)) * RS + ((lane >> 4) & 1) * 16;
    uint32_t boff = ((lane >> 4) & 1) * 8 * RS + (uint32_t)(lane & 7) * RS
                  + ((lane >> 3) & 1) * 16;

    float4 acc[12];
    #pragma unroll
    for (int t = 0; t < 12; t++) acc[t] = make_float4(0.f, 0.f, 0.f, 0.f);

    #pragma unroll
    for (int c = 0; c < 4; c++) {
        int kc0 = c * 32;
        if (c) __syncthreads();
        #pragma unroll
        for (int v = 0; v < 4; v++) {
            int f = tid + v * 256;
            int r = f >> 4, j = f & 15;
            int k = kc0 + j * 2;
            int n = n0 + r;
            float2 val = (n < NN && k < 102)
                ? *(const float2*)(node_rep + (size_t)n * NRD + k)
                : make_float2(0.f, 0.f);
            uint32_t hi, lo;
            split2(val.x, val.y, hi, lo);
            int off = r * RS + j * 4;
            *(uint32_t*)(sAhi + off) = hi;
            *(uint32_t*)(sAlo + off) = lo;
        }
        #pragma unroll
        for (int v = 0; v < 6; v++) {
            int f = tid + v * 256;
            int sel = f >= 768;
            int g = sel ? f - 768 : f;
            int o = g >> 2, q = g & 3;
            uint4 val = (sel ? g_W12lo : g_W12hi)[o * 16 + c * 4 + q];
            *(uint4*)((sel ? sBlo : sBhi) + o * RS + q * 16) = val;
        }
        __syncthreads();

        #pragma unroll
        for (int kc16 = 0; kc16 < 2; kc16++) {
            uint32_t ah[4], al[4];
            ldsm4(aHi + aoff + kc16 * 32, ah);
            ldsm4(aLo + aoff + kc16 * 32, al);
            #pragma unroll
            for (int tp = 0; tp < 6; tp++) {
                uint32_t bh[4], bl[4];
                uint32_t bo = (uint32_t)(nh * 96 + tp * 16) * RS + boff + kc16 * 32;
                ldsm4(bHi + bo, bh);
                ldsm4(bLo + bo, bl);
                mma_bf16(acc[tp * 2],     ah, bh[0], bh[1]);
                mma_bf16(acc[tp * 2],     ah, bl[0], bl[1]);
                mma_bf16(acc[tp * 2],     al, bh[0], bh[1]);
                mma_bf16(acc[tp * 2 + 1], ah, bh[2], bh[3]);
                mma_bf16(acc[tp * 2 + 1], ah, bl[2], bl[3]);
                mma_bf16(acc[tp * 2 + 1], al, bh[2], bh[3]);
            }
        }
    }

    float* outb = nh ? g_Q : g_P;
    int mrow = w4 * 16 + (lane >> 2);
    int kq = lane & 3;
    int node0 = n0 + mrow, node1 = node0 + 8;
    #pragma unroll
    for (int t = 0; t < 12; t++) {
        int col = t * 8 + kq * 2;
        if (node0 < NN)
            *(float2*)(outb + (size_t)node0 * 96 + col) = make_float2(acc[t].x, acc[t].y);
        if (node1 < NN)
            *(float2*)(outb + (size_t)node1 * 96 + col) = make_float2(acc[t].z, acc[t].w);
    }
}

// ---------------------------------------------------------------------------
// K5: edge_rep HMMA — R13 proven: B resident, single A buffer, 3 CTAs/SM,
//     with streaming hints (__ldcs attr, __stcs out) to protect P/Q in L2.
// ---------------------------------------------------------------------------
#define RS2 208
#define SB_AHI 0
#define SB_ALO 10240
#define SB_BHI 20480
#define SB_BLO (20480 + 96 * RS2)
#define SB_TOT (20480 + 2 * 96 * RS2)     // 60416 B

__global__ __launch_bounds__(256, 3) void edge_mma(const float* __restrict__ attr,
                                                   const float* __restrict__ b,
                                                   const int* __restrict__ ei,
                                                   float* __restrict__ out) {
    extern __shared__ __align__(16) char smem[];
    int tid = threadIdx.x, lane = tid & 31, w = tid >> 5;
    size_t e0 = (size_t)blockIdx.x * 128;

    uint32_t sb = smem_u32(smem);

    uint32_t aoff = (uint32_t)(w * 16 + (lane & 15)) * RS + ((lane >> 4) & 1) * 16;
    uint32_t boff = ((lane >> 4) & 1) * 8 * RS2 + (uint32_t)(lane & 7) * RS2
                  + ((lane >> 3) & 1) * 16;

    // ---- load full W3 (hi/lo) once ----
    #pragma unroll
    for (int v = 0; v < 9; v++) {
        int f = tid + v * 256;
        int sel = f >= 1152;
        int g = sel ? f - 1152 : f;
        int o = g / 12, q = g % 12;
        uint4 val = (sel ? g_W3lo : g_W3hi)[o * 12 + q];
        *(uint4*)(smem + (sel ? SB_BLO : SB_BHI) + o * RS2 + q * 16) = val;
    }

    float4 acc[12];
    #pragma unroll
    for (int t = 0; t < 12; t++) acc[t] = make_float4(0.f, 0.f, 0.f, 0.f);

    float4 pa[4];
    #pragma unroll
    for (int v = 0; v < 4; v++) {
        int f = tid + v * 256;
        int r = f >> 3, q4 = f & 7;
        pa[v] = __ldcs((const float4*)(attr + (e0 + r) * 96 + q4 * 4));
    }

    #pragma unroll
    for (int c = 0; c < 3; c++) {
        if (c) __syncthreads();                 // prev chunk's MMA reads done
        #pragma unroll
        for (int v = 0; v < 4; v++) {
            int f = tid + v * 256;
            int r = f >> 3, q4 = f & 7;
            uint2 hi, lo;
            split4(pa[v], hi, lo);
            int off = r * RS + q4 * 8;
            *(uint2*)(smem + SB_AHI + off) = hi;
            *(uint2*)(smem + SB_ALO + off) = lo;
        }
        __syncthreads();
        if (c < 2) {
            int kc0 = (c + 1) * 32;
            #pragma unroll
            for (int v = 0; v < 4; v++) {
                int f = tid + v * 256;
                int r = f >> 3, q4 = f & 7;
                pa[v] = __ldcs((const float4*)(attr + (e0 + r) * 96 + kc0 + q4 * 4));
            }
        }
        #pragma unroll
        for (int kc16 = 0; kc16 < 2; kc16++) {
            uint32_t ah[4], al[4];
            ldsm4(sb + SB_AHI + aoff + kc16 * 32, ah);
            ldsm4(sb + SB_ALO + aoff + kc16 * 32, al);
            uint32_t kbyte = (uint32_t)c * 64 + kc16 * 32;
            #pragma unroll
            for (int tp = 0; tp < 6; tp++) {
                uint32_t bh[4], bl[4];
                uint32_t bo = (uint32_t)(tp * 16) * RS2 + boff + kbyte;
                ldsm4(sb + SB_BHI + bo, bh);
                ldsm4(sb + SB_BLO + bo, bl);
                mma_bf16(acc[tp * 2],     ah, bh[0], bh[1]);
                mma_bf16(acc[tp * 2],     ah, bl[0], bl[1]);
                mma_bf16(acc[tp * 2],     al, bh[0], bh[1]);
                mma_bf16(acc[tp * 2 + 1], ah, bh[2], bh[3]);
                mma_bf16(acc[tp * 2 + 1], ah, bl[2], bl[3]);
                mma_bf16(acc[tp * 2 + 1], al, bh[2], bh[3]);
            }
        }
    }

    // epilogue
    int mrow = w * 16 + (lane >> 2);
    int kq = lane & 3;
    int er0 = (int)e0 + mrow;
    int er1 = er0 + 8;
    int r0i = ei[er0], c0i = ei[EE + er0];
    int r1i = ei[er1], c1i = ei[EE + er1];
    const float* P0 = g_P + (size_t)r0i * 96;
    const float* Q0 = g_Q + (size_t)c0i * 96;
    const float* P1 = g_P + (size_t)r1i * 96;
    const float* Q1 = g_Q + (size_t)c1i * 96;
    float* o0 = out + (size_t)er0 * 96;
    float* o1 = out + (size_t)er1 * 96;
    #pragma unroll
    for (int t = 0; t < 12; t++) {
        int col = t * 8 + kq * 2;
        float2 bv = *(const float2*)(b + col);
        float2 p0 = *(const float2*)(P0 + col), q0 = *(const float2*)(Q0 + col);
        __stcs((float2*)(o0 + col), make_float2(acc[t].x + p0.x + q0.x + bv.x,
                                                acc[t].y + p0.y + q0.y + bv.y));
        float2 p1 = *(const float2*)(P1 + col), q1 = *(const float2*)(Q1 + col);
        __stcs((float2*)(o1 + col), make_float2(acc[t].z + p1.x + q1.x + bv.x,
                                                acc[t].w + p1.y + q1.y + bv.y));
    }
}

// ---------------------------------------------------------------------------
extern "C" void kernel_launch(void* const* d_in, const int* in_sizes, int n_in,
                              void* d_out, int out_size) {
    const int*   change = (const int*)d_in[0];
    const int*   is_sup = (const int*)d_in[1];
    const int*   tails  = (const int*)d_in[3];
    const float* x      = (const float*)d_in[4];
    const int*   ei     = (const int*)d_in[5];
    const float* attr   = (const float*)d_in[6];
    const float* mask   = (const float*)d_in[7];
    const float* stail  = (const float*)d_in[9];
    const float* W      = (const float*)d_in[10];
    const float* b      = (const float*)d_in[11];

    float* node_out = (float*)d_out;
    float* edge_out = node_out + (size_t)NN * NRD;

    cudaFuncSetAttribute(edge_mma, cudaFuncAttributeMaxDynamicSharedMemorySize, SB_TOT);

    init_k    <<<(NN * 24 + 255) / 256, 256>>>(W);
    scatter_k <<<(EE * 12 + 255) / 256, 256>>>(ei, attr, mask, tails);
    finalize_k<<<(NN * 26 + 255) / 256, 256>>>(x, node_out, change, is_sup, stail);
    blend_k   <<<1, 1024>>>(change, is_sup, tails, node_out);
    pq_mma    <<<(NN + 63) / 64, 256>>>(node_out);
    edge_mma  <<<EE / 128, 256, SB_TOT>>>(attr, b, ei, edge_out);
}

// round 17
// speedup vs baseline: 1.1998x; 1.1998x over previous
#include <cuda_runtime.h>
#include <cuda_bf16.h>
#include <cstdint>

#define NN  100000
#define EE  800000
#define DD  96
#define NRD 102   // D + XD

// ---- scratch (device globals; no allocation allowed) ----
__device__ __align__(16) float4 g_num4[NN * 24];
__device__ float  g_den[NN];
__device__ int    g_tailflag[NN];
__device__ __align__(16) float g_P[NN * DD];
__device__ __align__(16) float g_Q[NN * DD];
__device__ __align__(16) uint4 g_W3hi[96 * 12];     // bf16 [96 o][96 k]
__device__ __align__(16) uint4 g_W3lo[96 * 12];
__device__ __align__(16) uint4 g_W12hi[192 * 16];   // bf16 [192 n][128 k pad]
__device__ __align__(16) uint4 g_W12lo[192 * 16];

__device__ __forceinline__ uint32_t smem_u32(const void* p) {
    uint32_t a;
    asm("{ .reg .u64 t; cvta.to.shared.u64 t, %1; cvt.u32.u64 %0, t; }" : "=r"(a) : "l"(p));
    return a;
}

// ---------------------------------------------------------------------------
// bf16 split helpers
// ---------------------------------------------------------------------------
__device__ __forceinline__ void split4(float4 v, uint2& hi, uint2& lo) {
    uint32_t h01, h23, l01, l23;
    asm("cvt.rn.bf16x2.f32 %0, %1, %2;" : "=r"(h01) : "f"(v.y), "f"(v.x));
    asm("cvt.rn.bf16x2.f32 %0, %1, %2;" : "=r"(h23) : "f"(v.w), "f"(v.z));
    float r0 = v.x - __uint_as_float(h01 << 16);
    float r1 = v.y - __uint_as_float(h01 & 0xFFFF0000u);
    float r2 = v.z - __uint_as_float(h23 << 16);
    float r3 = v.w - __uint_as_float(h23 & 0xFFFF0000u);
    asm("cvt.rn.bf16x2.f32 %0, %1, %2;" : "=r"(l01) : "f"(r1), "f"(r0));
    asm("cvt.rn.bf16x2.f32 %0, %1, %2;" : "=r"(l23) : "f"(r3), "f"(r2));
    hi = make_uint2(h01, h23); lo = make_uint2(l01, l23);
}
__device__ __forceinline__ void split2(float f0, float f1, uint32_t& hi, uint32_t& lo) {
    asm("cvt.rn.bf16x2.f32 %0, %1, %2;" : "=r"(hi) : "f"(f1), "f"(f0));
    float r0 = f0 - __uint_as_float(hi << 16);
    float r1 = f1 - __uint_as_float(hi & 0xFFFF0000u);
    asm("cvt.rn.bf16x2.f32 %0, %1, %2;" : "=r"(lo) : "f"(r1), "f"(r0));
}

// ---------------------------------------------------------------------------
// K0: zero accumulators + tail flags; block 0 pre-splits W3 and W1|W2
// ---------------------------------------------------------------------------
__global__ void init_k(const float* __restrict__ W) {
    if (blockIdx.x == 0) {
        for (int i = threadIdx.x; i < 96 * 24; i += 256) {
            int o = i / 24, q = i % 24;
            float4 v = *(const float4*)(W + o * 300 + 204 + q * 4);
            uint2 hi, lo;
            split4(v, hi, lo);
            *((uint2*)g_W3hi + o * 24 + q) = hi;
            *((uint2*)g_W3lo + o * 24 + q) = lo;
        }
        for (int i = threadIdx.x; i < 192 * 64; i += 256) {
            int n = i >> 6, kp = i & 63, k = kp * 2;
            const float* src = (n < 96) ? (W + n * 300 + k) : (W + (n - 96) * 300 + 102 + k);
            float f0 = (k < 102) ? src[0] : 0.f;
            float f1 = (k + 1 < 102) ? src[1] : 0.f;
            uint32_t hi, lo;
            split2(f0, f1, hi, lo);
            ((uint32_t*)g_W12hi)[i] = hi;
            ((uint32_t*)g_W12lo)[i] = lo;
        }
    }
    int i = blockIdx.x * 256 + threadIdx.x;
    if (i < NN * 24) g_num4[i] = make_float4(0.f, 0.f, 0.f, 0.f);
    if (i < NN)      { g_den[i] = 0.f; g_tailflag[i] = 0; }
}

// ---------------------------------------------------------------------------
// K1: masked scatter-sum — PROVEN form: one thread per (edge, quad),
//     lanes cover contiguous 16B quads (REDG line-coalesced).
// ---------------------------------------------------------------------------
__global__ void scatter_k(const int* __restrict__ ei,
                          const float* __restrict__ attr,
                          const float* __restrict__ mask,
                          const int* __restrict__ tails) {
    if (blockIdx.x == 0 && threadIdx.x < 128)
        g_tailflag[tails[threadIdx.x]] = 1;
    int i = blockIdx.x * 256 + threadIdx.x;
    if (i >= EE * 24) return;
    int e = i / 24;
    int q = i - e * 24;
    int c = ei[EE + e];
    float m = mask[e];
    float4 v = *(const float4*)(attr + (size_t)e * 96 + q * 4);
    float* dst = ((float*)g_num4) + (size_t)c * 96 + q * 4;
    asm volatile("red.global.add.v4.f32 [%0], {%1,%2,%3,%4};"
                 :: "l"(dst), "f"(v.x * m), "f"(v.y * m), "f"(v.z * m), "f"(v.w * m)
                 : "memory");
    if (q == 0) atomicAdd(&g_den[c], m);
}

// ---------------------------------------------------------------------------
// K2: finalize — num/(den+1) cols 0..95, x cols 96..101, tail blend fused
// ---------------------------------------------------------------------------
__global__ void finalize_k(const float* __restrict__ x,
                           float* __restrict__ node_out,
                           const int* __restrict__ change,
                           const int* __restrict__ is_support,
                           const float* __restrict__ stail) {
    int i = blockIdx.x * 256 + threadIdx.x;
    if (i >= NN * 26) return;
    int n = i / 26;
    int q = i - n * 26;
    bool bl = g_tailflag[n] && change[0] && !is_support[0];
    if (q < 24) {
        float inv = 1.f / (g_den[n] + 1.f);
        float4 v = g_num4[n * 24 + q];
        float o0 = v.x * inv, o1 = v.y * inv, o2 = v.z * inv, o3 = v.w * inv;
        int col = q * 4;
        if (bl) {
            o0 = 0.1f * stail[col]     + 0.9f * o0;
            o1 = 0.1f * stail[col + 1] + 0.9f * o1;
            o2 = 0.1f * stail[col + 2] + 0.9f * o2;
            o3 = 0.1f * stail[col + 3] + 0.9f * o3;
        }
        float* dst = node_out + (size_t)n * NRD + col;
        dst[0] = o0; dst[1] = o1; dst[2] = o2; dst[3] = o3;
    } else {
        int j0 = (q - 24) * 3;
        #pragma unroll
        for (int j = 0; j < 3; j++) {
            int d = 96 + j0 + j;
            float o = x[(size_t)n * 6 + j0 + j];
            if (bl) o = 0.1f * stail[d] + 0.9f * o;
            node_out[(size_t)n * NRD + d] = o;
        }
    }
}

// ---------------------------------------------------------------------------
// K3: tail-row blend — SUPPORT PATH ONLY; early-exit otherwise.
// ---------------------------------------------------------------------------
__global__ void blend_k(const int* __restrict__ change,
                        const int* __restrict__ is_support,
                        const int* __restrict__ tails,
                        float* __restrict__ node_out) {
    if (change[0] == 0 || is_support[0] == 0) return;
    const int TOT = 128 * NRD;
    int tid = threadIdx.x;
    float vals[13];
    int   addr[13];
    short dim[13];
    int cnt = 0;
    for (int i = tid; i < TOT; i += 1024) {
        int t = i / NRD, d = i - t * NRD;
        int node = tails[t];
        addr[cnt] = node * NRD + d;
        dim[cnt]  = (short)d;
        vals[cnt] = node_out[addr[cnt]];
        cnt++;
    }
    __shared__ float ssum[NRD];
    for (int d = tid; d < NRD; d += 1024) ssum[d] = 0.f;
    __syncthreads();
    for (int j = 0; j < cnt; j++) atomicAdd(&ssum[dim[j]], vals[j]);
    __syncthreads();
    for (int j = 0; j < cnt; j++)
        node_out[addr[j]] = ssum[dim[j]] * (1.f / 128.f);
}

// ---------------------------------------------------------------------------
// shared MMA helpers
// ---------------------------------------------------------------------------
__device__ __forceinline__ void ldsm4(uint32_t addr, uint32_t* r) {
    asm volatile("ldmatrix.sync.aligned.m8n8.x4.shared.b16 {%0,%1,%2,%3}, [%4];"
                 : "=r"(r[0]), "=r"(r[1]), "=r"(r[2]), "=r"(r[3]) : "r"(addr));
}
__device__ __forceinline__ void mma_bf16(float4& c, const uint32_t* a,
                                         uint32_t b0, uint32_t b1) {
    asm volatile(
        "mma.sync.aligned.m16n8k16.row.col.f32.bf16.bf16.f32 "
        "{%0,%1,%2,%3}, {%4,%5,%6,%7}, {%8,%9}, {%0,%1,%2,%3};"
        : "+f"(c.x), "+f"(c.y), "+f"(c.z), "+f"(c.w)
        : "r"(a[0]), "r"(a[1]), "r"(a[2]), "r"(a[3]), "r"(b0), "r"(b1));
}

#define RS 80           // A row stride bytes (64B data + 16B pad)

// ---------------------------------------------------------------------------
// K4: P|Q fused GEMM via HMMA bf16 3-term split (proven R13 version)
// ---------------------------------------------------------------------------
__global__ __launch_bounds__(256, 2) void pq_mma(const float* __restrict__ node_rep) {
    __shared__ __align__(16) char sAhi[64 * RS];
    __shared__ __align__(16) char sAlo[64 * RS];
    __shared__ __align__(16) char sBhi[192 * RS];
    __shared__ __align__(16) char sBlo[192 * RS];

    int tid = threadIdx.x, lane = tid & 31, w = tid >> 5;
    int n0 = blockIdx.x * 64;
    int w4 = w & 3, nh = w >> 2;

    uint32_t aHi = smem_u32(sAhi), aLo = smem_u32(sAlo);
    uint32_t bHi = smem_u32(sBhi), bLo = smem_u32(sBlo);

    uint32_t aoff = (uint32_t)(w4 * 16 + (lane & 15)) * RS + ((lane >> 4) & 1) * 16;
    uint32_t boff = ((lane >> 4) & 1) * 8 * RS + (uint32_t)(lane & 7) * RS
                  + ((lane >> 3) & 1) * 16;

    float4 acc[12];
    #pragma unroll
    for (int t = 0; t < 12; t++) acc[t] = make_float4(0.f, 0.f, 0.f, 0.f);

    #pragma unroll
    for (int c = 0; c < 4; c++) {
        int kc0 = c * 32;
        if (c) __syncthreads();
        #pragma unroll
        for (int v = 0; v < 4; v++) {
            int f = tid + v * 256;
            int r = f >> 4, j = f & 15;
            int k = kc0 + j * 2;
            int n = n0 + r;
            float2 val = (n < NN && k < 102)
                ? *(const float2*)(node_rep + (size_t)n * NRD + k)
                : make_float2(0.f, 0.f);
            uint32_t hi, lo;
            split2(val.x, val.y, hi, lo);
            int off = r * RS + j * 4;
            *(uint32_t*)(sAhi + off) = hi;
            *(uint32_t*)(sAlo + off) = lo;
        }
        #pragma unroll
        for (int v = 0; v < 6; v++) {
            int f = tid + v * 256;
            int sel = f >= 768;
            int g = sel ? f - 768 : f;
            int o = g >> 2, q = g & 3;
            uint4 val = (sel ? g_W12lo : g_W12hi)[o * 16 + c * 4 + q];
            *(uint4*)((sel ? sBlo : sBhi) + o * RS + q * 16) = val;
        }
        __syncthreads();

        #pragma unroll
        for (int kc16 = 0; kc16 < 2; kc16++) {
            uint32_t ah[4], al[4];
            ldsm4(aHi + aoff + kc16 * 32, ah);
            ldsm4(aLo + aoff + kc16 * 32, al);
            #pragma unroll
            for (int tp = 0; tp < 6; tp++) {
                uint32_t bh[4], bl[4];
                uint32_t bo = (uint32_t)(nh * 96 + tp * 16) * RS + boff + kc16 * 32;
                ldsm4(bHi + bo, bh);
                ldsm4(bLo + bo, bl);
                mma_bf16(acc[tp * 2],     ah, bh[0], bh[1]);
                mma_bf16(acc[tp * 2],     ah, bl[0], bl[1]);
                mma_bf16(acc[tp * 2],     al, bh[0], bh[1]);
                mma_bf16(acc[tp * 2 + 1], ah, bh[2], bh[3]);
                mma_bf16(acc[tp * 2 + 1], ah, bl[2], bl[3]);
                mma_bf16(acc[tp * 2 + 1], al, bh[2], bh[3]);
            }
        }
    }

    float* outb = nh ? g_Q : g_P;
    int mrow = w4 * 16 + (lane >> 2);
    int kq = lane & 3;
    int node0 = n0 + mrow, node1 = node0 + 8;
    #pragma unroll
    for (int t = 0; t < 12; t++) {
        int col = t * 8 + kq * 2;
        if (node0 < NN)
            *(float2*)(outb + (size_t)node0 * 96 + col) = make_float2(acc[t].x, acc[t].y);
        if (node1 < NN)
            *(float2*)(outb + (size_t)node1 * 96 + col) = make_float2(acc[t].z, acc[t].w);
    }
}

// ---------------------------------------------------------------------------
// K5: edge_rep HMMA — proven R13: B resident, single A buffer, 3 CTAs/SM.
// ---------------------------------------------------------------------------
#define RS2 208
#define SB_AHI 0
#define SB_ALO 10240
#define SB_BHI 20480
#define SB_BLO (20480 + 96 * RS2)
#define SB_TOT (20480 + 2 * 96 * RS2)     // 60416 B

__global__ __launch_bounds__(256, 3) void edge_mma(const float* __restrict__ attr,
                                                   const float* __restrict__ b,
                                                   const int* __restrict__ ei,
                                                   float* __restrict__ out) {
    extern __shared__ __align__(16) char smem[];
    int tid = threadIdx.x, lane = tid & 31, w = tid >> 5;
    size_t e0 = (size_t)blockIdx.x * 128;

    uint32_t sb = smem_u32(smem);

    uint32_t aoff = (uint32_t)(w * 16 + (lane & 15)) * RS + ((lane >> 4) & 1) * 16;
    uint32_t boff = ((lane >> 4) & 1) * 8 * RS2 + (uint32_t)(lane & 7) * RS2
                  + ((lane >> 3) & 1) * 16;

    // ---- load full W3 (hi/lo) once ----
    #pragma unroll
    for (int v = 0; v < 9; v++) {
        int f = tid + v * 256;
        int sel = f >= 1152;
        int g = sel ? f - 1152 : f;
        int o = g / 12, q = g % 12;
        uint4 val = (sel ? g_W3lo : g_W3hi)[o * 12 + q];
        *(uint4*)(smem + (sel ? SB_BLO : SB_BHI) + o * RS2 + q * 16) = val;
    }

    float4 acc[12];
    #pragma unroll
    for (int t = 0; t < 12; t++) acc[t] = make_float4(0.f, 0.f, 0.f, 0.f);

    float4 pa[4];
    #pragma unroll
    for (int v = 0; v < 4; v++) {
        int f = tid + v * 256;
        int r = f >> 3, q4 = f & 7;
        pa[v] = *(const float4*)(attr + (e0 + r) * 96 + q4 * 4);
    }

    #pragma unroll
    for (int c = 0; c < 3; c++) {
        if (c) __syncthreads();                 // prev chunk's MMA reads done
        #pragma unroll
        for (int v = 0; v < 4; v++) {
            int f = tid + v * 256;
            int r = f >> 3, q4 = f & 7;
            uint2 hi, lo;
            split4(pa[v], hi, lo);
            int off = r * RS + q4 * 8;
            *(uint2*)(smem + SB_AHI + off) = hi;
            *(uint2*)(smem + SB_ALO + off) = lo;
        }
        __syncthreads();
        if (c < 2) {
            int kc0 = (c + 1) * 32;
            #pragma unroll
            for (int v = 0; v < 4; v++) {
                int f = tid + v * 256;
                int r = f >> 3, q4 = f & 7;
                pa[v] = *(const float4*)(attr + (e0 + r) * 96 + kc0 + q4 * 4);
            }
        }
        #pragma unroll
        for (int kc16 = 0; kc16 < 2; kc16++) {
            uint32_t ah[4], al[4];
            ldsm4(sb + SB_AHI + aoff + kc16 * 32, ah);
            ldsm4(sb + SB_ALO + aoff + kc16 * 32, al);
            uint32_t kbyte = (uint32_t)c * 64 + kc16 * 32;
            #pragma unroll
            for (int tp = 0; tp < 6; tp++) {
                uint32_t bh[4], bl[4];
                uint32_t bo = (uint32_t)(tp * 16) * RS2 + boff + kbyte;
                ldsm4(sb + SB_BHI + bo, bh);
                ldsm4(sb + SB_BLO + bo, bl);
                mma_bf16(acc[tp * 2],     ah, bh[0], bh[1]);
                mma_bf16(acc[tp * 2],     ah, bl[0], bl[1]);
                mma_bf16(acc[tp * 2],     al, bh[0], bh[1]);
                mma_bf16(acc[tp * 2 + 1], ah, bh[2], bh[3]);
                mma_bf16(acc[tp * 2 + 1], ah, bl[2], bl[3]);
                mma_bf16(acc[tp * 2 + 1], al, bh[2], bh[3]);
            }
        }
    }

    // epilogue
    int mrow = w * 16 + (lane >> 2);
    int kq = lane & 3;
    int er0 = (int)e0 + mrow;
    int er1 = er0 + 8;
    int r0i = ei[er0], c0i = ei[EE + er0];
    int r1i = ei[er1], c1i = ei[EE + er1];
    const float* P0 = g_P + (size_t)r0i * 96;
    const float* Q0 = g_Q + (size_t)c0i * 96;
    const float* P1 = g_P + (size_t)r1i * 96;
    const float* Q1 = g_Q + (size_t)c1i * 96;
    float* o0 = out + (size_t)er0 * 96;
    float* o1 = out + (size_t)er1 * 96;
    #pragma unroll
    for (int t = 0; t < 12; t++) {
        int col = t * 8 + kq * 2;
        float2 bv = *(const float2*)(b + col);
        float2 p0 = *(const float2*)(P0 + col), q0 = *(const float2*)(Q0 + col);
        *(float2*)(o0 + col) = make_float2(acc[t].x + p0.x + q0.x + bv.x,
                                           acc[t].y + p0.y + q0.y + bv.y);
        float2 p1 = *(const float2*)(P1 + col), q1 = *(const float2*)(Q1 + col);
        *(float2*)(o1 + col) = make_float2(acc[t].z + p1.x + q1.x + bv.x,
                                           acc[t].w + p1.y + q1.y + bv.y);
    }
}

// ---------------------------------------------------------------------------
extern "C" void kernel_launch(void* const* d_in, const int* in_sizes, int n_in,
                              void* d_out, int out_size) {
    const int*   change = (const int*)d_in[0];
    const int*   is_sup = (const int*)d_in[1];
    const int*   tails  = (const int*)d_in[3];
    const float* x      = (const float*)d_in[4];
    const int*   ei     = (const int*)d_in[5];
    const float* attr   = (const float*)d_in[6];
    const float* mask   = (const float*)d_in[7];
    const float* stail  = (const float*)d_in[9];
    const float* W      = (const float*)d_in[10];
    const float* b      = (const float*)d_in[11];

    float* node_out = (float*)d_out;
    float* edge_out = node_out + (size_t)NN * NRD;

    cudaFuncSetAttribute(edge_mma, cudaFuncAttributeMaxDynamicSharedMemorySize, SB_TOT);

    init_k    <<<(NN * 24 + 255) / 256, 256>>>(W);
    scatter_k <<<(EE * 24 + 255) / 256, 256>>>(ei, attr, mask, tails);
    finalize_k<<<(NN * 26 + 255) / 256, 256>>>(x, node_out, change, is_sup, stail);
    blend_k   <<<1, 1024>>>(change, is_sup, tails, node_out);
    pq_mma    <<<(NN + 63) / 64, 256>>>(node_out);
    edge_mma  <<<EE / 128, 256, SB_TOT>>>(attr, b, ei, edge_out);
}